// round 9
// baseline (speedup 1.0000x reference)
#include <cuda_runtime.h>
#include <cstdint>

#define NB 8
#define SQ 2048
#define SK 2048
#define DD 512
#define DV 512
#define LDW 512     // all matrices have 512-float rows
#define TS2 36      // smem tile row stride in float2 (conflict-free LDS.64 frags)

__device__ float g_MT[NB * DV * DD];   // MT[b][v][d] = sum_s V[s,v]*K[s,d]
__device__ float g_X [NB * SQ * DV];   // X[b][q][v]  = (Q @ MT^T)/sqrt(512)
__device__ int   g_vl[SQ];

// ---------------------------------------------------------------------------
// tf32 helpers
// ---------------------------------------------------------------------------
__device__ __forceinline__ void split2(float x, uint32_t& h, uint32_t& l) {
    asm("cvt.rna.tf32.f32 %0, %1;" : "=r"(h) : "f"(x));
    float r = x - __uint_as_float(h);
    asm("cvt.rna.tf32.f32 %0, %1;" : "=r"(l) : "f"(r));
}

// D += A * B^T : m16n8k8 tf32 (A row-major 16x8, B [n][k])
#define MMA(c, a0, a1, a2, a3, b0, b1) asm volatile( \
    "mma.sync.aligned.m16n8k8.row.col.f32.tf32.tf32.f32 " \
    "{%0,%1,%2,%3}, {%4,%5,%6,%7}, {%8,%9}, {%0,%1,%2,%3};" \
    : "+f"((c)[0]), "+f"((c)[1]), "+f"((c)[2]), "+f"((c)[3]) \
    : "r"(a0), "r"(a1), "r"(a2), "r"(a3), "r"(b0), "r"(b1))

// ---------------------------------------------------------------------------
// Kernel 0: normalize valid_len (autodetect int64 vs int32 buffer layout)
// ---------------------------------------------------------------------------
__global__ void normalize_vlen_kernel(const int* __restrict__ raw)
{
    __shared__ int odd_nonzero;
    if (threadIdx.x == 0) odd_nonzero = 0;
    __syncthreads();
    int local = 0;
    for (int i = threadIdx.x; i < SQ; i += blockDim.x)
        if ((i & 1) && raw[i] != 0) local = 1;
    if (local) atomicOr(&odd_nonzero, 1);
    __syncthreads();
    const bool is32 = (odd_nonzero != 0);
    for (int q = threadIdx.x; q < SQ; q += blockDim.x)
        g_vl[q] = is32 ? raw[q] : raw[2 * q];
}

// ---------------------------------------------------------------------------
// tf32x3 GEMM via mma.sync, CTA tile 128x128, k-chunk 32.
// smem tiles hold (hi,lo) float2 per element, [row][k] stride TS2.
// 8 warps as 2(m) x 4(n); warp tile 64x32 = 4x4 m16n8k8 atoms.
// Per k-step: load ALL fragments (24x LDS.64), then 48 MMAs term-major
// (reuse distance 16 -> no RAW stalls on accumulators).
// ---------------------------------------------------------------------------
template <int TRANS>
__global__ __launch_bounds__(256, 2) void gemm_mma(
    const float* __restrict__ p0, const float* __restrict__ p1)
{
    extern __shared__ float2 sm2[];
    float2* At = sm2;                 // [128][TS2]
    float2* Bt = sm2 + 128 * TS2;

    const int tid = threadIdx.x, lane = tid & 31, wid = tid >> 5;
    const int wm = wid >> 2, wn = wid & 3;          // warp grid 2 x 4
    const int n0 = blockIdx.x * 128, m0 = blockIdx.y * 128, b = blockIdx.z;
    const int fg = lane >> 2, ft = lane & 3;        // frag row-group / k-offset

    const float* __restrict__ Ag;
    const float* __restrict__ Bg;
    float* __restrict__ Cb;
    int kT; float csc;
    if (TRANS) {   // A=V [s][v], B=K [s][d], C=g_MT [v][d]
        Ag = p0 + (size_t)b * SK * DV;  Bg = p1 + (size_t)b * SK * DD;
        Cb = g_MT + (size_t)b * DV * DD;  kT = SK;  csc = 1.0f;
    } else {       // A=Q [q][d], B=g_MT [v][d], C=g_X [q][v]
        Ag = p0 + (size_t)b * SQ * DD;  Bg = g_MT + (size_t)b * DV * DD;
        Cb = g_X + (size_t)b * SQ * DV;  kT = DD;  csc = 0.044194173824159216f;
    }

    float c[4][4][4];
#pragma unroll
    for (int i = 0; i < 4; i++)
#pragma unroll
        for (int j = 0; j < 4; j++)
#pragma unroll
            for (int u = 0; u < 4; u++) c[i][j][u] = 0.0f;

    const int nch = kT / 32;
    for (int ch = 0; ch < nch; ch++) {
        const int k0 = ch * 32;

        // ---- gmem loads BEFORE the barrier (latency overlap) ----
        float4 ga[4], gb[4];
        if (TRANS) {
            const int s = 4 * (lane & 7);              // k within chunk
            const int x = 16 * wid + 4 * (lane >> 3);  // m/n within tile
#pragma unroll
            for (int i = 0; i < 4; i++) {
                ga[i] = *(const float4*)&Ag[(size_t)(k0 + s + i) * LDW + m0 + x];
                gb[i] = *(const float4*)&Bg[(size_t)(k0 + s + i) * LDW + n0 + x];
            }
        } else {
#pragma unroll
            for (int i = 0; i < 4; i++) {
                const int f = tid + i * 256;           // float4 idx: 128 rows x 8
                const int row = f >> 3, col4 = f & 7;
                ga[i] = *(const float4*)&Ag[(size_t)(m0 + row) * LDW + k0 + col4 * 4];
                gb[i] = *(const float4*)&Bg[(size_t)(n0 + row) * LDW + k0 + col4 * 4];
            }
        }

        if (ch > 0) __syncthreads();   // previous chunk's MMAs done with smem

        // ---- split + store interleaved (hi,lo) pairs ----
        if (TRANS) {
            const int s = 4 * (lane & 7);
            const int x = 16 * wid + 4 * (lane >> 3);
            const float* fa = (const float*)ga;
            const float* fb = (const float*)gb;
#pragma unroll
            for (int j = 0; j < 4; j++) {
                // column j of the 4(k) x 4(x) micro-block -> row x+j, k s..s+3
                uint32_t h0, l0, h1, l1, h2, l2, h3, l3;
                split2(fa[j],      h0, l0);  split2(fa[4 + j],  h1, l1);
                split2(fa[8 + j],  h2, l2);  split2(fa[12 + j], h3, l3);
                float2* pr = &At[(size_t)(x + j) * TS2 + s];
                *(uint4*)(pr)     = make_uint4(h0, l0, h1, l1);
                *(uint4*)(pr + 2) = make_uint4(h2, l2, h3, l3);
                split2(fb[j],      h0, l0);  split2(fb[4 + j],  h1, l1);
                split2(fb[8 + j],  h2, l2);  split2(fb[12 + j], h3, l3);
                pr = &Bt[(size_t)(x + j) * TS2 + s];
                *(uint4*)(pr)     = make_uint4(h0, l0, h1, l1);
                *(uint4*)(pr + 2) = make_uint4(h2, l2, h3, l3);
            }
        } else {
#pragma unroll
            for (int i = 0; i < 4; i++) {
                const int f = tid + i * 256;
                const int row = f >> 3, col4 = f & 7;
                uint32_t h0, l0, h1, l1, h2, l2, h3, l3;
                split2(ga[i].x, h0, l0);  split2(ga[i].y, h1, l1);
                split2(ga[i].z, h2, l2);  split2(ga[i].w, h3, l3);
                float2* pr = &At[(size_t)row * TS2 + col4 * 4];
                *(uint4*)(pr)     = make_uint4(h0, l0, h1, l1);
                *(uint4*)(pr + 2) = make_uint4(h2, l2, h3, l3);
                split2(gb[i].x, h0, l0);  split2(gb[i].y, h1, l1);
                split2(gb[i].z, h2, l2);  split2(gb[i].w, h3, l3);
                pr = &Bt[(size_t)row * TS2 + col4 * 4];
                *(uint4*)(pr)     = make_uint4(h0, l0, h1, l1);
                *(uint4*)(pr + 2) = make_uint4(h2, l2, h3, l3);
            }
        }
        __syncthreads();

        // ---- MMA: 4 k-steps of 8 ----
#pragma unroll
        for (int ks = 0; ks < 4; ks++) {
            const int kk = ks * 8;

            // B fragments: 4 an x {b0,b1} x (hi,lo)  -> 8 LDS.64
            uint32_t bh[4][2], bl[4][2];
#pragma unroll
            for (int an = 0; an < 4; an++) {
                const float2* p = &Bt[(size_t)(wn * 32 + an * 8 + fg) * TS2 + kk + ft];
                uint2 u0 = *(const uint2*)(p);
                uint2 u1 = *(const uint2*)(p + 4);
                bh[an][0] = u0.x; bl[an][0] = u0.y;
                bh[an][1] = u1.x; bl[an][1] = u1.y;
            }
            // A fragments: 4 am x {a0..a3} x (hi,lo) -> 16 LDS.64
            uint32_t ah[4][4], al[4][4];
#pragma unroll
            for (int am = 0; am < 4; am++) {
                const float2* p = &At[(size_t)(wm * 64 + am * 16 + fg) * TS2 + kk + ft];
                uint2 u0 = *(const uint2*)(p);
                uint2 u1 = *(const uint2*)(p + 8 * TS2);
                uint2 u2 = *(const uint2*)(p + 4);
                uint2 u3 = *(const uint2*)(p + 8 * TS2 + 4);
                ah[am][0] = u0.x; al[am][0] = u0.y;
                ah[am][1] = u1.x; al[am][1] = u1.y;
                ah[am][2] = u2.x; al[am][2] = u2.y;
                ah[am][3] = u3.x; al[am][3] = u3.y;
            }

            // term-major: 16 independent MMAs between accumulator reuses
#pragma unroll
            for (int am = 0; am < 4; am++)
#pragma unroll
                for (int an = 0; an < 4; an++)
                    MMA(c[am][an], ah[am][0], ah[am][1], ah[am][2], ah[am][3],
                        bh[an][0], bh[an][1]);
#pragma unroll
            for (int am = 0; am < 4; am++)
#pragma unroll
                for (int an = 0; an < 4; an++)
                    MMA(c[am][an], al[am][0], al[am][1], al[am][2], al[am][3],
                        bh[an][0], bh[an][1]);
#pragma unroll
            for (int am = 0; am < 4; am++)
#pragma unroll
                for (int an = 0; an < 4; an++)
                    MMA(c[am][an], ah[am][0], ah[am][1], ah[am][2], ah[am][3],
                        bl[an][0], bl[an][1]);
        }
    }

    // ---- epilogue ----
#pragma unroll
    for (int am = 0; am < 4; am++) {
        const int mr = m0 + wm * 64 + am * 16 + fg;
#pragma unroll
        for (int an = 0; an < 4; an++) {
            const int nc = n0 + wn * 32 + an * 8 + ft * 2;
            float2 w0 = make_float2(c[am][an][0] * csc, c[am][an][1] * csc);
            float2 w1 = make_float2(c[am][an][2] * csc, c[am][an][3] * csc);
            *(float2*)&Cb[(size_t)mr * LDW + nc]       = w0;
            *(float2*)&Cb[(size_t)(mr + 8) * LDW + nc] = w1;
        }
    }
}

// ---------------------------------------------------------------------------
// Kernel C: mask (col > valid_len[q] -> -1e6) + row softmax over 512 cols.
// ---------------------------------------------------------------------------
__global__ __launch_bounds__(256) void softmax_kernel(float* __restrict__ out)
{
    const int b = blockIdx.y, q0 = blockIdx.x * 32;
    const int tid = threadIdx.x, lane = tid & 31, warp = tid >> 5;
    const int r0 = warp * 4;
    const float* __restrict__ Xb = g_X + (size_t)b * SQ * DV;

    float acc[4][16];
#pragma unroll
    for (int i = 0; i < 4; i++) {
        const float* row = Xb + (size_t)(q0 + r0 + i) * DV;
#pragma unroll
        for (int j = 0; j < 16; j++) acc[i][j] = row[lane + 32 * j];
    }

#pragma unroll
    for (int i = 0; i < 4; i++) {
        const int q = q0 + r0 + i;
        const int vl = g_vl[q];
        float rmax = -3.402823e38f;
#pragma unroll
        for (int j = 0; j < 16; j++) {
            const int cidx = lane + 32 * j;
            float x = acc[i][j];
            if (cidx > vl) x = -1000000.0f;
            acc[i][j] = x;
            rmax = fmaxf(rmax, x);
        }
#pragma unroll
        for (int off = 16; off > 0; off >>= 1)
            rmax = fmaxf(rmax, __shfl_xor_sync(0xFFFFFFFFu, rmax, off));
        float rsum = 0.0f;
#pragma unroll
        for (int j = 0; j < 16; j++) {
            const float e = __expf(acc[i][j] - rmax);
            acc[i][j] = e;
            rsum += e;
        }
#pragma unroll
        for (int off = 16; off > 0; off >>= 1)
            rsum += __shfl_xor_sync(0xFFFFFFFFu, rsum, off);
        const float inv = 1.0f / rsum;
        float* __restrict__ orow = out + (size_t)b * SQ * DV + (size_t)q * DV;
#pragma unroll
        for (int j = 0; j < 16; j++)
            orow[lane + 32 * j] = acc[i][j] * inv;
    }
}

#define GEMM_SMEM (2 * 128 * TS2 * 8)   // 73728 bytes

extern "C" void kernel_launch(void* const* d_in, const int* in_sizes, int n_in,
                              void* d_out, int out_size)
{
    const float* K   = (const float*)d_in[0];
    const float* V   = (const float*)d_in[1];
    const float* Q   = (const float*)d_in[2];
    const int*   vlr = (const int*)d_in[3];
    float*       out = (float*)d_out;

    cudaFuncSetAttribute(gemm_mma<1>, cudaFuncAttributeMaxDynamicSharedMemorySize, GEMM_SMEM);
    cudaFuncSetAttribute(gemm_mma<0>, cudaFuncAttributeMaxDynamicSharedMemorySize, GEMM_SMEM);

    normalize_vlen_kernel<<<1, 1024>>>(vlr);

    dim3 gA(DD / 128, DV / 128, NB);                 // (4, 4, 8): MT[v][d]
    gemm_mma<1><<<gA, 256, GEMM_SMEM>>>(V, K);

    dim3 gB(DV / 128, SQ / 128, NB);                 // (4, 16, 8): X[q][v]
    gemm_mma<0><<<gB, 256, GEMM_SMEM>>>(Q, nullptr);

    dim3 gC(SQ / 32, NB);                            // (64, 8)
    softmax_kernel<<<gC, 256>>>(out);
}

// round 11
// speedup vs baseline: 1.4554x; 1.4554x over previous
#include <cuda_runtime.h>
#include <cstdint>

#define NB 8
#define SQ 2048
#define SK 2048
#define DD 512
#define DV 512
#define LDW 512       // all matrices have 512-float rows
#define TSTRIDE 36    // smem tile row stride in floats (conflict-free frag loads)
#define KSPLIT 4      // split-K factor for kernel A

__device__ float g_P [KSPLIT * NB * DV * DD];  // split-K partials for MT
__device__ float g_MT[NB * DV * DD];           // MT[b][v][d] = sum_s V[s,v]*K[s,d]
__device__ float g_X [NB * SQ * DV];           // X[b][q][v] = (Q @ MT^T)/sqrt(512)
__device__ int   g_vl[SQ];

// ---------------------------------------------------------------------------
// tf32 helpers
// ---------------------------------------------------------------------------
__device__ __forceinline__ void split2(float x, uint32_t& h, uint32_t& l) {
    asm("cvt.rna.tf32.f32 %0, %1;" : "=r"(h) : "f"(x));
    float r = x - __uint_as_float(h);
    asm("cvt.rna.tf32.f32 %0, %1;" : "=r"(l) : "f"(r));
}
__device__ __forceinline__ void split4(float4 g, uint4& h, uint4& l) {
    split2(g.x, h.x, l.x); split2(g.y, h.y, l.y);
    split2(g.z, h.z, l.z); split2(g.w, h.w, l.w);
}

// D += A * B^T : m16n8k8 tf32 (A row-major 16x8, B [n][k])
#define MMA(c, a, b) asm volatile( \
    "mma.sync.aligned.m16n8k8.row.col.f32.tf32.tf32.f32 " \
    "{%0,%1,%2,%3}, {%4,%5,%6,%7}, {%8,%9}, {%0,%1,%2,%3};" \
    : "+f"((c)[0]), "+f"((c)[1]), "+f"((c)[2]), "+f"((c)[3]) \
    : "r"((a)[0]), "r"((a)[1]), "r"((a)[2]), "r"((a)[3]), \
      "r"((b)[0]), "r"((b)[1]))

__device__ __forceinline__ void ldfragA(const float* T, int r0, int k0, int lane,
                                        uint32_t a[4]) {
    const float* p = T + (size_t)(r0 + (lane >> 2)) * TSTRIDE + k0 + (lane & 3);
    a[0] = __float_as_uint(p[0]);
    a[1] = __float_as_uint(p[8 * TSTRIDE]);
    a[2] = __float_as_uint(p[4]);
    a[3] = __float_as_uint(p[8 * TSTRIDE + 4]);
}
__device__ __forceinline__ void ldfragB(const float* T, int n0, int k0, int lane,
                                        uint32_t b[2]) {
    const float* p = T + (size_t)(n0 + (lane >> 2)) * TSTRIDE + k0 + (lane & 3);
    b[0] = __float_as_uint(p[0]);
    b[1] = __float_as_uint(p[4]);
}

// ---------------------------------------------------------------------------
// Kernel 0: normalize valid_len (autodetect int64 vs int32 buffer layout)
// ---------------------------------------------------------------------------
__global__ void normalize_vlen_kernel(const int* __restrict__ raw)
{
    __shared__ int odd_nonzero;
    if (threadIdx.x == 0) odd_nonzero = 0;
    __syncthreads();
    int local = 0;
    for (int i = threadIdx.x; i < SQ; i += blockDim.x)
        if ((i & 1) && raw[i] != 0) local = 1;
    if (local) atomicOr(&odd_nonzero, 1);
    __syncthreads();
    const bool is32 = (odd_nonzero != 0);
    for (int q = threadIdx.x; q < SQ; q += blockDim.x)
        g_vl[q] = is32 ? raw[q] : raw[2 * q];
}

// ---------------------------------------------------------------------------
// Split-K reduce: g_MT = sum over KSPLIT partials (deterministic order)
// ---------------------------------------------------------------------------
__global__ __launch_bounds__(256) void reduce_mt_kernel()
{
    const int idx = blockIdx.x * blockDim.x + threadIdx.x;   // float4 index
    const float4* p0 = (const float4*)g_P + idx;
    const size_t stride4 = (size_t)NB * DV * DD / 4;
    float4 a = p0[0], b = p0[stride4], c = p0[2 * stride4], d = p0[3 * stride4];
    float4 r;
    r.x = (a.x + b.x) + (c.x + d.x);
    r.y = (a.y + b.y) + (c.y + d.y);
    r.z = (a.z + b.z) + (c.z + d.z);
    r.w = (a.w + b.w) + (c.w + d.w);
    ((float4*)g_MT)[idx] = r;
}

// ---------------------------------------------------------------------------
// tf32x3 GEMM via mma.sync, CTA tile 128x128, k-chunk 32 (R8 base).
//   TRANS=1 (kernel A): A'=V^T, B'=K^T (gmem [k][x], transpose-on-load),
//                       split-K x4: blockIdx.z = b*KSPLIT + seg, partial out.
//   TRANS=0 (kernel B): A'=Q, B'=MT (gmem [x][k], straight), C = X*csc.
// 8 warps as 2(m) x 4(n); warp tile 64x32 = 4x4 m16n8k8 atoms.
// ---------------------------------------------------------------------------
template <int TRANS>
__global__ __launch_bounds__(256, 2) void gemm_mma(
    const float* __restrict__ p0, const float* __restrict__ p1)
{
    extern __shared__ float smf[];
    float* Ah = smf;
    float* Al = smf + 128 * TSTRIDE;
    float* Bh = smf + 2 * 128 * TSTRIDE;
    float* Bl = smf + 3 * 128 * TSTRIDE;

    const int tid = threadIdx.x, lane = tid & 31, wid = tid >> 5;
    const int wm = wid >> 2, wn = wid & 3;       // warp grid 2 x 4
    const int n0 = blockIdx.x * 128, m0 = blockIdx.y * 128;

    const float* __restrict__ Ag;
    const float* __restrict__ Bg;
    float* __restrict__ Cb;
    int kT; float csc;
    if (TRANS) {   // A=V [s][v], B=K [s][d], C partial -> g_P[seg][b]
        const int b = blockIdx.z >> 2, seg = blockIdx.z & 3;
        const size_t soff = (size_t)seg * (SK / KSPLIT) * LDW;
        Ag = p0 + (size_t)b * SK * DV + soff;
        Bg = p1 + (size_t)b * SK * DD + soff;
        Cb = g_P + ((size_t)seg * NB + b) * DV * DD;
        kT = SK / KSPLIT;  csc = 1.0f;
    } else {       // A=Q [q][d], B=g_MT [v][d], C=g_X [q][v]
        const int b = blockIdx.z;
        Ag = p0 + (size_t)b * SQ * DD;
        Bg = g_MT + (size_t)b * DV * DD;
        Cb = g_X + (size_t)b * SQ * DV;
        kT = DD;  csc = 0.044194173824159216f;
    }

    float c[4][4][4];
#pragma unroll
    for (int i = 0; i < 4; i++)
#pragma unroll
        for (int j = 0; j < 4; j++)
#pragma unroll
            for (int u = 0; u < 4; u++) c[i][j][u] = 0.0f;

    const int nch = kT / 32;
    for (int ch = 0; ch < nch; ch++) {
        const int k0 = ch * 32;

        // ---- gmem loads BEFORE the barrier (latency overlap) ----
        float4 ga[4], gb[4];
        if (TRANS) {
            const int s = 4 * (lane & 7);              // k within chunk
            const int x = 16 * wid + 4 * (lane >> 3);  // m/n within tile
#pragma unroll
            for (int i = 0; i < 4; i++) {
                ga[i] = *(const float4*)&Ag[(size_t)(k0 + s + i) * LDW + m0 + x];
                gb[i] = *(const float4*)&Bg[(size_t)(k0 + s + i) * LDW + n0 + x];
            }
        } else {
#pragma unroll
            for (int i = 0; i < 4; i++) {
                const int f = tid + i * 256;           // float4 idx: 128 rows x 8
                const int row = f >> 3, col4 = f & 7;
                ga[i] = *(const float4*)&Ag[(size_t)(m0 + row) * LDW + k0 + col4 * 4];
                gb[i] = *(const float4*)&Bg[(size_t)(n0 + row) * LDW + k0 + col4 * 4];
            }
        }

        if (ch > 0) __syncthreads();   // previous chunk's MMAs done with smem

        // ---- split + store to smem tiles ----
        if (TRANS) {
            const int s = 4 * (lane & 7);
            const int x = 16 * wid + 4 * (lane >> 3);
            const float* fa = (const float*)ga;
            const float* fb = (const float*)gb;
#pragma unroll
            for (int j = 0; j < 4; j++) {
                float4 colA = make_float4(fa[j], fa[4 + j], fa[8 + j], fa[12 + j]);
                float4 colB = make_float4(fb[j], fb[4 + j], fb[8 + j], fb[12 + j]);
                uint4 h, l;
                split4(colA, h, l);
                *(uint4*)&Ah[(size_t)(x + j) * TSTRIDE + s] = h;
                *(uint4*)&Al[(size_t)(x + j) * TSTRIDE + s] = l;
                split4(colB, h, l);
                *(uint4*)&Bh[(size_t)(x + j) * TSTRIDE + s] = h;
                *(uint4*)&Bl[(size_t)(x + j) * TSTRIDE + s] = l;
            }
        } else {
#pragma unroll
            for (int i = 0; i < 4; i++) {
                const int f = tid + i * 256;
                const int row = f >> 3, col4 = f & 7;
                uint4 h, l;
                split4(ga[i], h, l);
                *(uint4*)&Ah[(size_t)row * TSTRIDE + col4 * 4] = h;
                *(uint4*)&Al[(size_t)row * TSTRIDE + col4 * 4] = l;
                split4(gb[i], h, l);
                *(uint4*)&Bh[(size_t)row * TSTRIDE + col4 * 4] = h;
                *(uint4*)&Bl[(size_t)row * TSTRIDE + col4 * 4] = l;
            }
        }
        __syncthreads();

        // ---- MMA: 4 k-steps of 8, tf32x3 ----
        // Per am: hh x4an, lh x4an, hl x4an -> accumulator reuse distance 4,
        // no extra fragment liveness vs R8 (R9's regression cause avoided).
#pragma unroll
        for (int ks = 0; ks < 4; ks++) {
            const int kk = ks * 8;
            uint32_t bh[4][2], bl[4][2];
#pragma unroll
            for (int an = 0; an < 4; an++) {
                const int nb = wn * 32 + an * 8;
                ldfragB(Bh, nb, kk, lane, bh[an]);
                ldfragB(Bl, nb, kk, lane, bl[an]);
            }
#pragma unroll
            for (int am = 0; am < 4; am++) {
                const int mr = wm * 64 + am * 16;
                uint32_t ah[4], al[4];
                ldfragA(Ah, mr, kk, lane, ah);
                ldfragA(Al, mr, kk, lane, al);
#pragma unroll
                for (int an = 0; an < 4; an++) MMA(c[am][an], ah, bh[an]);
#pragma unroll
                for (int an = 0; an < 4; an++) MMA(c[am][an], al, bh[an]);
#pragma unroll
                for (int an = 0; an < 4; an++) MMA(c[am][an], ah, bl[an]);
            }
        }
    }

    // ---- epilogue ----
#pragma unroll
    for (int am = 0; am < 4; am++) {
        const int mr = m0 + wm * 64 + am * 16 + (lane >> 2);
#pragma unroll
        for (int an = 0; an < 4; an++) {
            const int nc = n0 + wn * 32 + an * 8 + (lane & 3) * 2;
            float2 w0 = make_float2(c[am][an][0] * csc, c[am][an][1] * csc);
            float2 w1 = make_float2(c[am][an][2] * csc, c[am][an][3] * csc);
            *(float2*)&Cb[(size_t)mr * LDW + nc]       = w0;
            *(float2*)&Cb[(size_t)(mr + 8) * LDW + nc] = w1;
        }
    }
}

// ---------------------------------------------------------------------------
// Kernel C: mask (col > valid_len[q] -> -1e6) + row softmax over 512 cols.
// ---------------------------------------------------------------------------
__global__ __launch_bounds__(256) void softmax_kernel(float* __restrict__ out)
{
    const int b = blockIdx.y, q0 = blockIdx.x * 32;
    const int tid = threadIdx.x, lane = tid & 31, warp = tid >> 5;
    const int r0 = warp * 4;
    const float* __restrict__ Xb = g_X + (size_t)b * SQ * DV;

    float acc[4][16];
#pragma unroll
    for (int i = 0; i < 4; i++) {
        const float* row = Xb + (size_t)(q0 + r0 + i) * DV;
#pragma unroll
        for (int j = 0; j < 16; j++) acc[i][j] = row[lane + 32 * j];
    }

#pragma unroll
    for (int i = 0; i < 4; i++) {
        const int q = q0 + r0 + i;
        const int vl = g_vl[q];
        float rmax = -3.402823e38f;
#pragma unroll
        for (int j = 0; j < 16; j++) {
            const int cidx = lane + 32 * j;
            float x = acc[i][j];
            if (cidx > vl) x = -1000000.0f;
            acc[i][j] = x;
            rmax = fmaxf(rmax, x);
        }
#pragma unroll
        for (int off = 16; off > 0; off >>= 1)
            rmax = fmaxf(rmax, __shfl_xor_sync(0xFFFFFFFFu, rmax, off));
        float rsum = 0.0f;
#pragma unroll
        for (int j = 0; j < 16; j++) {
            const float e = __expf(acc[i][j] - rmax);
            acc[i][j] = e;
            rsum += e;
        }
#pragma unroll
        for (int off = 16; off > 0; off >>= 1)
            rsum += __shfl_xor_sync(0xFFFFFFFFu, rsum, off);
        const float inv = 1.0f / rsum;
        float* __restrict__ orow = out + (size_t)b * SQ * DV + (size_t)q * DV;
#pragma unroll
        for (int j = 0; j < 16; j++)
            orow[lane + 32 * j] = acc[i][j] * inv;
    }
}

#define GEMM_SMEM (4 * 128 * TSTRIDE * 4)   // 73728 bytes

extern "C" void kernel_launch(void* const* d_in, const int* in_sizes, int n_in,
                              void* d_out, int out_size)
{
    const float* K   = (const float*)d_in[0];
    const float* V   = (const float*)d_in[1];
    const float* Q   = (const float*)d_in[2];
    const int*   vlr = (const int*)d_in[3];
    float*       out = (float*)d_out;

    cudaFuncSetAttribute(gemm_mma<1>, cudaFuncAttributeMaxDynamicSharedMemorySize, GEMM_SMEM);
    cudaFuncSetAttribute(gemm_mma<0>, cudaFuncAttributeMaxDynamicSharedMemorySize, GEMM_SMEM);

    normalize_vlen_kernel<<<1, 1024>>>(vlr);

    dim3 gA(DD / 128, DV / 128, NB * KSPLIT);        // (4, 4, 32): partials
    gemm_mma<1><<<gA, 256, GEMM_SMEM>>>(V, K);

    reduce_mt_kernel<<<(NB * DV * DD / 4) / 256, 256>>>();   // 2048 blocks

    dim3 gB(DV / 128, SQ / 128, NB);                 // (4, 16, 8): X[q][v]
    gemm_mma<0><<<gB, 256, GEMM_SMEM>>>(Q, nullptr);

    dim3 gC(SQ / 32, NB);                            // (64, 8)
    softmax_kernel<<<gC, 256>>>(out);
}